// round 9
// baseline (speedup 1.0000x reference)
#include <cuda_runtime.h>
#include <cuda_bf16.h>
#include <cstdint>

// Problem constants: B=16 graphs, N=4096 nodes/graph, 64 features, k=10.
#define KNN_K      10
#define BGRAPHS    16
#define FEATS      64
#define MAX_TOTAL  65536
#define NODES      4096
#define NPAIR      (NODES / 2)
#define QPB        256
#define NBUCKET    1024
#define BUCKET_W   (8.0f / NBUCKET)   // x-bucket width (range [-4,4])
#define EXIT_MARGIN 1e-4f             // covers f32 cancellation in computed d2

// Scratch (device globals: no allocation allowed in kernel_launch)
__device__ float  g_sum[MAX_TOTAL * FEATS];    // 16 MB accumulators
__device__ int    g_cnt[MAX_TOTAL];            // reverse-degree counts
__device__ int    g_nbr[MAX_TOTAL * KNN_K];    // knn neighbor lists (global idx)
__device__ float4 g_spos[MAX_TOTAL];           // x-sorted positions {x,y,z,|p|^2}
__device__ int    g_sidx[MAX_TOTAL];           // sorted-rank -> original local idx

// ---------- packed f32x2 helpers (sm_103a) ----------
__device__ __forceinline__ uint64_t pack2(float a, float b) {
    uint64_t r; asm("mov.b64 %0, {%1, %2};" : "=l"(r) : "f"(a), "f"(b)); return r;
}
__device__ __forceinline__ void unpack2(float& lo, float& hi, uint64_t v) {
    asm("mov.b64 {%0, %1}, %2;" : "=f"(lo), "=f"(hi) : "l"(v));
}
__device__ __forceinline__ uint64_t mul2(uint64_t a, uint64_t b) {
    uint64_t r; asm("mul.rn.f32x2 %0, %1, %2;" : "=l"(r) : "l"(a), "l"(b)); return r;
}
__device__ __forceinline__ uint64_t add2(uint64_t a, uint64_t b) {
    uint64_t r; asm("add.rn.f32x2 %0, %1, %2;" : "=l"(r) : "l"(a), "l"(b)); return r;
}
__device__ __forceinline__ uint64_t fma2(uint64_t a, uint64_t b, uint64_t c) {
    uint64_t r; asm("fma.rn.f32x2 %0, %1, %2, %3;" : "=l"(r) : "l"(a), "l"(b), "l"(c)); return r;
}

// sorted-ascending ripple insert of one u64 key (d2_bits<<32 | orig_idx):
// exact (distance, then original-index) order == jax.lax.top_k tie semantics.
#define INS(cin) do {                                                     \
    uint64_t c_ = (cin);                                                  \
    _Pragma("unroll")                                                     \
    for (int t_ = 0; t_ < KNN_K; ++t_) {                                  \
        uint64_t mn_ = (c_ < kd[t_]) ? c_ : kd[t_];                       \
        uint64_t mx_ = (c_ < kd[t_]) ? kd[t_] : c_;                       \
        kd[t_] = mn_; c_ = mx_;                                           \
    }                                                                     \
    thr = __uint_as_float((unsigned)(kd[KNN_K - 1] >> 32));               \
} while (0)

// distance + conditional insert for one pair; exports x0_,x1_.
#define PAIR_BODY(jp, x0_, x1_) \
    ulonglong2 xy = pxy[jp];                                              \
    ulonglong2 zw = pzw[jp];                                              \
    uint64_t dot = mul2(qx2, xy.x);                                       \
    dot = fma2(qy2, xy.y, dot);                                           \
    dot = fma2(qz2, zw.x, dot);                                           \
    uint64_t s2  = add2(qsq2, zw.y);                                      \
    uint64_t d2p = fma2(m2, dot, s2);                                     \
    float lo, hi; unpack2(lo, hi, d2p);                                   \
    float x0_, x1_; unpack2(x0_, x1_, xy.x);                              \
    if (fminf(lo, hi) < thr) {                                            \
        int j0_ = (jp) * 2;                                               \
        if (lo < thr && j0_ != qr) {                                      \
            uint64_t key = ((uint64_t)__float_as_uint(lo) << 32)          \
                         | (unsigned)ssid[j0_];                           \
            INS(key);                                                     \
        }                                                                 \
        if (hi < thr && (j0_ + 1) != qr) {                                \
            uint64_t key = ((uint64_t)__float_as_uint(hi) << 32)          \
                         | (unsigned)ssid[j0_ + 1];                       \
            INS(key);                                                     \
        }                                                                 \
    }

__device__ __forceinline__ int xbucket(float x) {
    int bk = (int)floorf((x + 4.0f) * (NBUCKET / 8.0f));
    return max(0, min(NBUCKET - 1, bk));
}

// ---------------------------------------------------------------------------
// K0: counting-sort each graph's points into 1024 x-buckets (within-bucket
// order atomic-arbitrary; exactness preserved: selection is a total order on
// (d2, orig_idx)). w = |p|^2 with exact reference rounding (no contraction).
// ---------------------------------------------------------------------------
__global__ void sort_kernel(const float* __restrict__ pos) {
    __shared__ int cnt[NBUCKET];
    __shared__ int tsum[256];
    __shared__ int off[NBUCKET];

    const int b   = blockIdx.x;
    const int tid = threadIdx.x;        // 256 threads
    const float* pg = pos + (size_t)b * NODES * 3;

#pragma unroll
    for (int i = 0; i < NBUCKET / 256; ++i) cnt[tid + i * 256] = 0;
    __syncthreads();

    for (int j = tid; j < NODES; j += 256)
        atomicAdd(&cnt[xbucket(pg[3 * j])], 1);
    __syncthreads();

    // two-level exclusive prefix: thread t owns bins [4t, 4t+4)
    {
        int c0 = cnt[4 * tid], c1 = cnt[4 * tid + 1];
        int c2 = cnt[4 * tid + 2], c3 = cnt[4 * tid + 3];
        tsum[tid] = c0 + c1 + c2 + c3;
        __syncthreads();
        for (int d = 1; d < 256; d <<= 1) {
            int v = (tid >= d) ? tsum[tid - d] : 0;
            __syncthreads();
            tsum[tid] += v;
            __syncthreads();
        }
        int base = tsum[tid] - (c0 + c1 + c2 + c3);
        off[4 * tid]     = base;
        off[4 * tid + 1] = base + c0;
        off[4 * tid + 2] = base + c0 + c1;
        off[4 * tid + 3] = base + c0 + c1 + c2;
    }
    __syncthreads();

    for (int j = tid; j < NODES; j += 256) {
        float x = pg[3 * j], y = pg[3 * j + 1], z = pg[3 * j + 2];
        float w = __fadd_rn(__fadd_rn(__fmul_rn(x, x), __fmul_rn(y, y)),
                            __fmul_rn(z, z));        // == jnp.sum(pos*pos)
        int p = atomicAdd(&off[xbucket(x)], 1);
        g_spos[b * NODES + p] = make_float4(x, y, z, w);
        g_sidx[b * NODES + p] = j;
    }
}

// ---------------------------------------------------------------------------
// K1: x-sorted kNN, center-out alternating expansion, exact early exit,
// transverse-radius lane grouping.
//   core: exactly the tile's 128 pairs (each query's closest x-ranks first).
//   expansion: alternate 4-pair chunks up/down with per-direction votes.
//     Candidates arrive in ~increasing distance for every lane -> transient
//     inserts collapse toward k, and both thresholds tighten before either
//     direction goes far.
// Exit proof (bucket-monotone order): any rank beyond the last processed has
// x >= x_last - BUCKET_W, so if for all lanes
//   max(|x_last - qx| - BUCKET_W, 0)^2 >= thr + EXIT_MARGIN
// no future candidate in that direction can beat any lane's 10th distance.
// thr = +inf until a lane holds 10 -> no premature exit.
// d2 is bit-identical to the reference ((qsq+w) - 2*dot, 2*dot exact).
// ---------------------------------------------------------------------------
__global__ void __launch_bounds__(QPB) knn_kernel(int dummy) {
    extern __shared__ float4 sm[];
    float4* sxy  = sm;                    // NPAIR {x0,x1,y0,y1}
    float4* szw  = sm + NPAIR;            // NPAIR {z0,z1,w0,w1}
    int*    ssid = (int*)(sm + NODES);    // NODES rank -> orig idx
    __shared__ uint64_t skey[QPB];        // (t_bits<<32)|rank for lane grouping

    const int tilesPerGraph = NODES / QPB;  // 16
    const int b    = blockIdx.x / tilesPerGraph;
    const int tile = blockIdx.x % tilesPerGraph;
    const int tid  = threadIdx.x;
    const int gbase = b * NODES;

    // ---- fused zeroing of accumulators + counts (block-flat region) ----
    {
        float4 z = make_float4(0.f, 0.f, 0.f, 0.f);
        int nb = blockIdx.x * QPB;
        float4* dst = reinterpret_cast<float4*>(g_sum) + (size_t)nb * (FEATS / 4);
#pragma unroll
        for (int i = 0; i < 16; ++i) dst[i * QPB + tid] = z;
        g_cnt[nb + tid] = 0;
    }

    // ---- stage sorted positions (pair-transposed) + rank->orig idx ----
    for (int jp = tid; jp < NPAIR; jp += QPB) {
        float4 a = g_spos[gbase + 2 * jp];
        float4 c = g_spos[gbase + 2 * jp + 1];
        sxy[jp] = make_float4(a.x, c.x, a.y, c.y);
        szw[jp] = make_float4(a.z, c.z, a.w, c.w);
    }
    for (int j = tid; j < NODES; j += QPB)
        ssid[j] = g_sidx[gbase + j];
    __syncthreads();

    // ---- lane grouping: bitonic sort tile queries by transverse radius ----
    {
        int   qr0 = tile * QPB + tid;
        float4 xy0 = sxy[qr0 >> 1];
        float4 zw0 = szw[qr0 >> 1];
        float xq = (qr0 & 1) ? xy0.y : xy0.x;
        float wq = (qr0 & 1) ? zw0.w : zw0.z;
        float t  = fmaxf(wq - xq * xq, 0.0f);
        skey[tid] = ((uint64_t)__float_as_uint(t) << 32) | (unsigned)qr0;
    }
    __syncthreads();
    for (int k = 2; k <= QPB; k <<= 1) {
        for (int j = k >> 1; j > 0; j >>= 1) {
            int ixj = tid ^ j;
            if (ixj > tid) {
                uint64_t a = skey[tid], c = skey[ixj];
                bool asc = ((tid & k) == 0);
                if ((a > c) == asc) { skey[tid] = c; skey[ixj] = a; }
            }
            __syncthreads();
        }
    }

    // ---- own query: permuted rank ----
    const int qr = (int)(unsigned)(skey[tid] & 0xffffffffu);
    float qx, qy, qz, qsq;
    {
        float4 xy = sxy[qr >> 1];
        float4 zw = szw[qr >> 1];
        if (qr & 1) { qx = xy.y; qy = xy.w; qz = zw.y; qsq = zw.w; }
        else        { qx = xy.x; qy = xy.z; qz = zw.x; qsq = zw.z; }
    }
    const uint64_t qx2  = pack2(qx, qx);
    const uint64_t qy2  = pack2(qy, qy);
    const uint64_t qz2  = pack2(qz, qz);
    const uint64_t qsq2 = pack2(qsq, qsq);
    const uint64_t m2   = pack2(-2.0f, -2.0f);

    uint64_t kd[KNN_K];
#pragma unroll
    for (int t = 0; t < KNN_K; ++t) kd[t] = 0x7f800000ffffffffULL;
    float thr = __int_as_float(0x7f800000);

    const ulonglong2* pxy = reinterpret_cast<const ulonglong2*>(sxy);
    const ulonglong2* pzw = reinterpret_cast<const ulonglong2*>(szw);

    // ---- core: exactly the tile's pairs ----
    const int tb_p = (tile * QPB) >> 1;          // 128 pairs
#pragma unroll 4
    for (int jp = tb_p; jp < tb_p + (QPB >> 1); ++jp) {
        PAIR_BODY(jp, cx0, cx1);
        (void)cx0; (void)cx1;
    }

    // ---- alternating outward expansion, per-direction exact exits ----
    {
        int  up = tb_p + (QPB >> 1);
        int  dn = tb_p - 1;
        bool upAct = (up < NPAIR);
        bool dnAct = (dn >= 0);
        while (upAct || dnAct) {
            if (upAct) {
                float lastx = 0.0f;
#pragma unroll
                for (int i = 0; i < 4; ++i) {
                    int jp = up + i;
                    if (jp < NPAIR) {
                        PAIR_BODY(jp, ux0, ux1);
                        (void)ux1;
                        lastx = ux0;
                    }
                }
                up += 4;
                float dnn = fmaxf(lastx - qx - BUCKET_W, 0.0f);
                if (__all_sync(0xffffffffu, dnn * dnn >= thr + EXIT_MARGIN) ||
                    up >= NPAIR) upAct = false;
            }
            if (dnAct) {
                float lastx = 0.0f;
#pragma unroll
                for (int i = 0; i < 4; ++i) {
                    int jp = dn - i;
                    if (jp >= 0) {
                        PAIR_BODY(jp, dx0, dx1);
                        (void)dx0;
                        lastx = dx1;
                    }
                }
                dn -= 4;
                float dnn = fmaxf(qx - lastx - BUCKET_W, 0.0f);
                if (__all_sync(0xffffffffu, dnn * dnn >= thr + EXIT_MARGIN) ||
                    dn < 0) dnAct = false;
            }
        }
    }

    // ---- write neighbor list for this query's ORIGINAL node id ----
    const int my_oid = gbase + ssid[qr];
#pragma unroll
    for (int t = 0; t < KNN_K; ++t)
        g_nbr[my_oid * KNN_K + t] = gbase + (int)(unsigned)kd[t];
}

// ---------------------------------------------------------------------------
// K2: scatter x[query] into g_sum[neighbor] with vectorized L2 reductions,
// plus reverse-degree counting (lane c==0 of each 16-lane query group).
// ---------------------------------------------------------------------------
__global__ void scatter_kernel(const float* __restrict__ x, int total) {
    int t = blockIdx.x * blockDim.x + threadIdx.x;
    int q = t >> 4;
    int c = t & 15;
    if (q >= total) return;

    float4 v = reinterpret_cast<const float4*>(x)[q * (FEATS / 4) + c];
    const int* nb = &g_nbr[q * KNN_K];

#pragma unroll
    for (int n = 0; n < KNN_K; ++n) {
        int j = nb[n];
        float* p = g_sum + (size_t)j * FEATS + c * 4;
        asm volatile("red.global.add.v4.f32 [%0], {%1, %2, %3, %4};"
                     :: "l"(p), "f"(v.x), "f"(v.y), "f"(v.z), "f"(v.w)
                     : "memory");
        if (c == 0)
            asm volatile("red.global.add.u32 [%0], %1;"
                         :: "l"(&g_cnt[j]), "r"(1) : "memory");
    }
}

// ---------------------------------------------------------------------------
// K3: out[r] = sum_d | x[r,d] - sum[r,d] / max(cnt[r],1) |   (warp per node)
// ---------------------------------------------------------------------------
__global__ void out_kernel(const float* __restrict__ x, float* __restrict__ out,
                           int total) {
    int node = (blockIdx.x * blockDim.x + threadIdx.x) >> 5;
    int lane = threadIdx.x & 31;
    if (node >= total) return;

    float c   = (float)g_cnt[node];
    float inv = 1.0f / fmaxf(c, 1.0f);

    const float* xr = x + (size_t)node * FEATS;
    const float* sr = g_sum + (size_t)node * FEATS;

    float acc = fabsf(xr[lane]      - sr[lane]      * inv)
              + fabsf(xr[lane + 32] - sr[lane + 32] * inv);
#pragma unroll
    for (int o = 16; o > 0; o >>= 1) acc += __shfl_xor_sync(0xffffffffu, acc, o);
    if (lane == 0) out[node] = acc;
}

// ---------------------------------------------------------------------------
extern "C" void kernel_launch(void* const* d_in, const int* in_sizes, int n_in,
                              void* d_out, int out_size) {
    const float* x   = (const float*)d_in[0];   // [total, 64] fp32
    const float* pos = (const float*)d_in[1];   // [total, 3]  fp32

    const int total = in_sizes[0] / FEATS;      // 65536
    float* out = (float*)d_out;

    // K0: per-graph counting sort by x (1024 buckets)
    sort_kernel<<<BGRAPHS, 256>>>(pos);

    // K1: kNN (smem: 64KB pos + 16KB idx dynamic, +2KB static skey)
    size_t smem = (size_t)NODES * sizeof(float4) + NODES * sizeof(int);
    cudaFuncSetAttribute(knn_kernel, cudaFuncAttributeMaxDynamicSharedMemorySize,
                         (int)smem);
    knn_kernel<<<total / QPB, QPB, smem>>>(0);

    // K2: vectorized atomic scatter + counts (16 lanes per query)
    int threads2 = total * 16;
    scatter_kernel<<<(threads2 + 127) / 128, 128>>>(x, total);

    // K3: finalize L1 norm (warp per node)
    out_kernel<<<(total * 32 + 255) / 256, 256>>>(x, out, total);
}